// round 10
// baseline (speedup 1.0000x reference)
#include <cuda_runtime.h>
#include <cuda_fp16.h>
#include <cstdint>

#define BATCH 8192
#define NREF  2048
#define KDIM  256
#define MT    128             // M rows per mtile (4 warps x 32 rows)
#define NM    64              // number of mtiles
#define NPACK 1024            // packed columns total (2 refs each)
#define NT    32              // packed cols per work item
#define CHUNKS 32             // items per mtile (NPACK / NT)
#define GRID  296             // persistent CTAs (2 per SM x 148)
#define ROWB  512             // bytes per packed-col row (256 halves)
#define LDB   528             // padded smem row stride (bytes)

// g_Bp[j][k']: k-permuted f16 (1-2R[2j,k]) + 1024*(1-2R[2j+1,k])
__device__ __half g_Bp[NPACK * KDIM];
__device__ float  g_cntR[NREF];
__device__ int    g_cnt[NM];          // per-mtile work counters

struct Smem {
    char  B[2][NT * LDB];     // 2 x 16896 B
    float cntR[NREF];         // all 2048 cntR (8192 B)
    int   bc[2];              // work-item broadcast
};
#define SMEM_SZ (int)sizeof(Smem)

// ---------------------------------------------------------------------------
__device__ __forceinline__ uint32_t s2u(const void* p) {
    uint32_t a;
    asm("{ .reg .u64 t; cvta.to.shared.u64 t, %1; cvt.u32.u64 %0, t; }" : "=r"(a) : "l"(p));
    return a;
}
__device__ __forceinline__ void cpa16(uint32_t dst, const void* src) {
    asm volatile("cp.async.cg.shared.global [%0], [%1], 16;" :: "r"(dst), "l"(src));
}
template <int N>
__device__ __forceinline__ void cpwait() {
    asm volatile("cp.async.wait_group %0;" :: "n"(N) : "memory");
}
__device__ __forceinline__ void mma_f16f32(float* c, const uint32_t* a,
                                           uint32_t b0, uint32_t b1) {
    asm volatile(
        "mma.sync.aligned.m16n8k16.row.col.f32.f16.f16.f32 "
        "{%0,%1,%2,%3},{%4,%5,%6,%7},{%8,%9},{%0,%1,%2,%3};"
        : "+f"(c[0]), "+f"(c[1]), "+f"(c[2]), "+f"(c[3])
        : "r"(a[0]), "r"(a[1]), "r"(a[2]), "r"(a[3]), "r"(b0), "r"(b1));
}
__device__ __forceinline__ uint32_t packh2(float x, float y) {
    __half2 h = __floats2half2_rn(x, y);
    return *reinterpret_cast<uint32_t*>(&h);
}
__device__ __forceinline__ void decode_min(float acc, float2 cr, float& rmin) {
    float d1 = rintf(acc * (1.0f / 1024.0f));      // |d0|/1024 <= 0.25 -> no ties
    float d0 = fmaf(d1, -1024.0f, acc);            // exact
    rmin = fminf(rmin, fminf(d0 + cr.x, d1 + cr.y));
}

// ---------------------------------------------------------------------------
// Kernel 1 (prep): out init; counters reset; pack ref pairs (radix 1024) with
// the k-permutation that makes A fragments contiguous float4 loads; cntR.
// Permutation within each 16-k group: logical k = 4q+r (q=0..3, r=0..3)
//  -> physical half index: r<2 ? 2q+r : 8+2q+(r-2). Same perm on A (via
// contiguous float4) and B => dot products unchanged.
// ---------------------------------------------------------------------------
__global__ void prep_kernel(const float* __restrict__ R, int* __restrict__ outi) {
    int i = blockIdx.x * 256 + threadIdx.x;

    if (i < BATCH) outi[i] = 0x7f800000;   // +inf bits
    if (i < NM) g_cnt[i] = 0;              // reset work counters

    if (i < NPACK * 64) {                  // one logical k-quad per thread
        int j = i >> 6, c = i & 63;        // packed col j, quad c (k = 4c..4c+3)
        int g16 = c >> 2, q = c & 3;       // 16-k group, q within group
        float4 r0 = *reinterpret_cast<const float4*>(R + (size_t)(2 * j) * KDIM + c * 4);
        float4 r1 = *reinterpret_cast<const float4*>(R + (size_t)(2 * j + 1) * KDIM + c * 4);
        uint32_t lo = packh2(1025.f - 2.f * r0.x - 2048.f * r1.x,
                             1025.f - 2.f * r0.y - 2048.f * r1.y);
        uint32_t hi = packh2(1025.f - 2.f * r0.z - 2048.f * r1.z,
                             1025.f - 2.f * r0.w - 2048.f * r1.w);
        uint32_t* bp = reinterpret_cast<uint32_t*>(g_Bp);
        bp[j * 128 + g16 * 8 + q]     = lo;   // phys halves 2q,2q+1
        bp[j * 128 + g16 * 8 + 4 + q] = hi;   // phys halves 8+2q,8+2q+1
    } else if (i < NPACK * 64 + NREF * 32) {
        int t = i - NPACK * 64;
        int w = t >> 5, lane = t & 31;
        float s = 0.f;
        #pragma unroll
        for (int k = lane; k < KDIM; k += 32) s += R[w * KDIM + k];
        #pragma unroll
        for (int o = 16; o; o >>= 1) s += __shfl_xor_sync(0xffffffffu, s, o);
        if (lane == 0) g_cntR[w] = s;
    }
}

// ---------------------------------------------------------------------------
// Kernel 2 (main): persistent work-stealing HMMA GEMM on packed B.
// Items = (mtile, 32-col chunk); per-mtile counters; home-mtile affinity
// keeps A fragments resident across a CTA's items.
// ---------------------------------------------------------------------------
__device__ __forceinline__ void load_B(Smem& sm, int chunk, int buf, int tid) {
    const char* src = (const char*)g_Bp + (size_t)chunk * NT * ROWB;
    #pragma unroll
    for (int j = 0; j < 8; j++) {            // 1024 x 16B chunks / 128 threads
        int i = tid + j * 128;
        int r = i >> 5, c = i & 31;
        cpa16(s2u(&sm.B[buf][r * LDB + c * 16]), src + (size_t)r * ROWB + c * 16);
    }
    asm volatile("cp.async.commit_group;" ::: "memory");
}

__global__ void __launch_bounds__(128, 2) hamming_ws(const float* __restrict__ S,
                                                     int* __restrict__ outi) {
    extern __shared__ __align__(16) char smraw[];
    Smem& sm = *reinterpret_cast<Smem*>(smraw);

    const int tid  = threadIdx.x;
    const int wid  = tid >> 5;
    const int lane = tid & 31;
    const int g    = lane >> 2;
    const int q    = lane & 3;
    const int home = blockIdx.x & (NM - 1);

    uint32_t a[2][16][4];
    int scan = 0;                       // meaningful in thread 0 only

    // ---- fetch item 0 ----
    if (tid == 0) {
        int m = -1, c = -1;
        while (scan < NM) {
            int mm = home + scan; if (mm >= NM) mm -= NM;
            int t = atomicAdd(&g_cnt[mm], 1);
            if (t < CHUNKS) { m = mm; c = t; break; }
            scan++;
        }
        sm.bc[0] = m; sm.bc[1] = c;
    }
    __syncthreads();
    int cur_m = sm.bc[0], cur_c = sm.bc[1];
    if (cur_m < 0) return;              // uniform: no work at all

    load_B(sm, cur_c, 0, tid);

    // cntR (all 2048) into smem once
    for (int i = tid; i < NREF / 4; i += 128)
        *reinterpret_cast<float4*>(&sm.cntR[i * 4]) =
            *reinterpret_cast<const float4*>(&g_cntR[i * 4]);

    // A fragments for cur_m (contiguous float4 thanks to k-permutation)
    auto loadA = [&](int m) {
        #pragma unroll
        for (int mt = 0; mt < 2; mt++) {
            const float* rowLo = S + ((size_t)(m * MT + wid * 32 + mt * 16 + g)) * KDIM;
            const float* rowHi = rowLo + 8 * KDIM;
            #pragma unroll
            for (int ks = 0; ks < 16; ks++) {
                float4 v0 = *reinterpret_cast<const float4*>(rowLo + ks * 16 + q * 4);
                float4 v1 = *reinterpret_cast<const float4*>(rowHi + ks * 16 + q * 4);
                a[mt][ks][0] = packh2(v0.x, v0.y);
                a[mt][ks][2] = packh2(v0.z, v0.w);
                a[mt][ks][1] = packh2(v1.x, v1.y);
                a[mt][ks][3] = packh2(v1.z, v1.w);
            }
        }
    };
    loadA(cur_m);

    const float2* cr2 = reinterpret_cast<const float2*>(sm.cntR);
    float rmin[2][2] = {{__int_as_float(0x7f800000), __int_as_float(0x7f800000)},
                        {__int_as_float(0x7f800000), __int_as_float(0x7f800000)}};

    auto flush = [&](int m) {
        #pragma unroll
        for (int mt = 0; mt < 2; mt++)
            #pragma unroll
            for (int h = 0; h < 2; h++) {
                float v = rmin[mt][h];
                v = fminf(v, __shfl_xor_sync(0xffffffffu, v, 1));
                v = fminf(v, __shfl_xor_sync(0xffffffffu, v, 2));
                if (q == 0)
                    atomicMin(&outi[m * MT + wid * 32 + mt * 16 + h * 8 + g],
                              __float_as_int(v));
                rmin[mt][h] = __int_as_float(0x7f800000);
            }
    };

    int buf = 0;
    for (;;) {
        // ---- fetch next item ----
        if (tid == 0) {
            int m = -1, c = -1;
            while (scan < NM) {
                int mm = home + scan; if (mm >= NM) mm -= NM;
                int t = atomicAdd(&g_cnt[mm], 1);
                if (t < CHUNKS) { m = mm; c = t; break; }
                scan++;
            }
            sm.bc[0] = m; sm.bc[1] = c;
        }
        __syncthreads();
        int nm = sm.bc[0], nc = sm.bc[1];

        if (nm >= 0) { load_B(sm, nc, buf ^ 1, tid); cpwait<1>(); }
        else         { cpwait<0>(); }
        __syncthreads();

        // ---- MMA on current item (32 packed cols = 4 n-blocks) ----
        const char* Bb = sm.B[buf];
        float c[2][4][4];
        #pragma unroll
        for (int mt = 0; mt < 2; mt++)
            #pragma unroll
            for (int u = 0; u < 4; u++)
                c[mt][u][0] = c[mt][u][1] = c[mt][u][2] = c[mt][u][3] = 0.f;

        #pragma unroll
        for (int ks = 0; ks < 16; ks++) {
            int kb = ks * 32 + q * 4;
            uint32_t b0[4], b1[4];
            #pragma unroll
            for (int u = 0; u < 4; u++) {
                const char* bp = &Bb[(u * 8 + g) * LDB + kb];
                b0[u] = *reinterpret_cast<const uint32_t*>(bp);
                b1[u] = *reinterpret_cast<const uint32_t*>(bp + 16);
            }
            #pragma unroll
            for (int u = 0; u < 4; u++) {
                mma_f16f32(c[0][u], a[0][ks], b0[u], b1[u]);
                mma_f16f32(c[1][u], a[1][ks], b0[u], b1[u]);
            }
        }

        // ---- decode epilogue ----
        #pragma unroll
        for (int u = 0; u < 4; u++) {
            int gcol = cur_c * NT + u * 8 + q * 2;
            float2 cra = cr2[gcol];
            float2 crb = cr2[gcol + 1];
            #pragma unroll
            for (int mt = 0; mt < 2; mt++) {
                decode_min(c[mt][u][0], cra, rmin[mt][0]);
                decode_min(c[mt][u][1], crb, rmin[mt][0]);
                decode_min(c[mt][u][2], cra, rmin[mt][1]);
                decode_min(c[mt][u][3], crb, rmin[mt][1]);
            }
        }
        __syncthreads();   // consumed sm.B[buf]; safe to refill next iteration

        if (nm < 0) break;
        if (nm != cur_m) { flush(cur_m); loadA(nm); }
        cur_m = nm; cur_c = nc; buf ^= 1;
    }
    flush(cur_m);
}

// ---------------------------------------------------------------------------
extern "C" void kernel_launch(void* const* d_in, const int* in_sizes, int n_in,
                              void* d_out, int out_size) {
    const float* states = (const float*)d_in[0];
    const float* R      = (const float*)d_in[1];
    int* outi           = (int*)d_out;

    const int prepThreads = NPACK * 64 + NREF * 32;   // 131072
    prep_kernel<<<(prepThreads + 255) / 256, 256>>>(R, outi);

    cudaFuncSetAttribute(hamming_ws, cudaFuncAttributeMaxDynamicSharedMemorySize, SMEM_SZ);
    hamming_ws<<<GRID, 128, SMEM_SZ>>>(states, outi);
}

// round 11
// speedup vs baseline: 1.9811x; 1.9811x over previous
#include <cuda_runtime.h>
#include <cuda_fp16.h>
#include <cstdint>

#define BATCH 8192
#define NREF  2048
#define KDIM  256
#define MT    128              // M rows per mtile
#define NM    64               // mtiles
// tensor path: refs 0..1535 -> 768 packed cols; per quarter 192 cols
#define NPACKT 768
#define NQ    192              // packed cols per CTA (quarter)
#define NT    32               // packed cols per tile
#define NTILES 6
// popc path: refs 1536..2047; 128 per CTA (quarter)
#define PREFS 512
#define PR    128
#define ROWB  512              // bytes per packed-col row (256 halves)
#define LDB   528              // padded smem row stride

__device__ __half    g_Bp[NPACKT * KDIM];   // packed radix-1024 B (k-permuted)
__device__ float     g_cntR[2 * NPACKT];    // cntR for tensor refs 0..1535
__device__ uint32_t  g_Sbits[BATCH * 8];    // S rows as 256-bit
__device__ uint32_t  g_Rbits[PREFS * 8];    // R rows 1536.. as 256-bit

struct Smem {
    char     B[2][NT * LDB];   // 2 x 16896
    float    cntR[2 * NQ];     // 384 floats
    uint32_t Rbits[PR * 8];    // 4096 B
};
#define SMEM_SZ (int)sizeof(Smem)

// ---------------------------------------------------------------------------
__device__ __forceinline__ uint32_t s2u(const void* p) {
    uint32_t a;
    asm("{ .reg .u64 t; cvta.to.shared.u64 t, %1; cvt.u32.u64 %0, t; }" : "=r"(a) : "l"(p));
    return a;
}
__device__ __forceinline__ void cpa16(uint32_t dst, const void* src) {
    asm volatile("cp.async.cg.shared.global [%0], [%1], 16;" :: "r"(dst), "l"(src));
}
template <int N>
__device__ __forceinline__ void cpwait() {
    asm volatile("cp.async.wait_group %0;" :: "n"(N) : "memory");
}
__device__ __forceinline__ void mma_f16f32(float* c, const uint32_t* a,
                                           uint32_t b0, uint32_t b1) {
    asm volatile(
        "mma.sync.aligned.m16n8k16.row.col.f32.f16.f16.f32 "
        "{%0,%1,%2,%3},{%4,%5,%6,%7},{%8,%9},{%0,%1,%2,%3};"
        : "+f"(c[0]), "+f"(c[1]), "+f"(c[2]), "+f"(c[3])
        : "r"(a[0]), "r"(a[1]), "r"(a[2]), "r"(a[3]), "r"(b0), "r"(b1));
}
__device__ __forceinline__ uint32_t packh2(float x, float y) {
    __half2 h = __floats2half2_rn(x, y);
    return *reinterpret_cast<uint32_t*>(&h);
}
__device__ __forceinline__ void decode_min(float acc, float2 cr, float& rmin) {
    float d1 = rintf(acc * (1.0f / 1024.0f));
    float d0 = fmaf(d1, -1024.0f, acc);
    rmin = fminf(rmin, fminf(d0 + cr.x, d1 + cr.y));
}

// ---------------------------------------------------------------------------
// Prep: out init; pack B (radix-1024, k-permuted) for refs 0..1535; cntR for
// those refs; bit-pack all S rows; bit-pack R rows 1536..2047.
// Ranges are warp-aligned so ballot branches are warp-uniform.
// ---------------------------------------------------------------------------
#define PREP_T (49152 + 49152 + 262144 + 16384)   // 376832

__global__ void prep_kernel(const float* __restrict__ S, const float* __restrict__ R,
                            int* __restrict__ outi) {
    int i = blockIdx.x * 256 + threadIdx.x;
    int lane = threadIdx.x & 31;

    if (i < BATCH) outi[i] = 0x7f800000;   // +inf bits

    if (i < 49152) {                       // B pack: packed col j < 768
        int j = i >> 6, c = i & 63;
        int g16 = c >> 2, q = c & 3;
        float4 r0 = *reinterpret_cast<const float4*>(R + (size_t)(2 * j) * KDIM + c * 4);
        float4 r1 = *reinterpret_cast<const float4*>(R + (size_t)(2 * j + 1) * KDIM + c * 4);
        uint32_t lo = packh2(1025.f - 2.f * r0.x - 2048.f * r1.x,
                             1025.f - 2.f * r0.y - 2048.f * r1.y);
        uint32_t hi = packh2(1025.f - 2.f * r0.z - 2048.f * r1.z,
                             1025.f - 2.f * r0.w - 2048.f * r1.w);
        uint32_t* bp = reinterpret_cast<uint32_t*>(g_Bp);
        bp[j * 128 + g16 * 8 + q]     = lo;
        bp[j * 128 + g16 * 8 + 4 + q] = hi;
    } else if (i < 98304) {                // cntR for refs 0..1535
        int t = i - 49152;
        int w = t >> 5;
        float s = 0.f;
        #pragma unroll
        for (int k = lane; k < KDIM; k += 32) s += R[w * KDIM + k];
        #pragma unroll
        for (int o = 16; o; o >>= 1) s += __shfl_xor_sync(0xffffffffu, s, o);
        if (lane == 0) g_cntR[w] = s;
    } else if (i < 360448) {               // S bits: one warp per row
        int row = (i - 98304) >> 5;
        #pragma unroll
        for (int w = 0; w < 8; w++) {
            float v = S[(size_t)row * KDIM + w * 32 + lane];
            uint32_t word = __ballot_sync(0xffffffffu, v != 0.0f);
            if (lane == w) g_Sbits[row * 8 + w] = word;
        }
    } else if (i < PREP_T) {               // R bits: refs 1536..2047
        int pr = (i - 360448) >> 5;
        #pragma unroll
        for (int w = 0; w < 8; w++) {
            float v = R[(size_t)(PREFS * 3 + pr) * KDIM + w * 32 + lane];
            uint32_t word = __ballot_sync(0xffffffffu, v != 0.0f);
            if (lane == w) g_Rbits[pr * 8 + w] = word;
        }
    }
}

// ---------------------------------------------------------------------------
// Main: heterogeneous CTA. Warps 0-7: HMMA on packed B (16 rows each).
// Warps 8-11: bit-XOR/POPC Hamming on refs 1536.. (one lane per row).
// ---------------------------------------------------------------------------
__device__ __forceinline__ void load_B(Smem& sm, int gcol0, int buf, int tid) {
    const char* src = (const char*)g_Bp + (size_t)gcol0 * ROWB;
    #pragma unroll
    for (int j = 0; j < 4; j++) {            // 1024 x 16B chunks / 256 threads
        int i = tid + j * 256;
        int r = i >> 5, c = i & 31;
        cpa16(s2u(&sm.B[buf][r * LDB + c * 16]), src + (size_t)r * ROWB + c * 16);
    }
    asm volatile("cp.async.commit_group;" ::: "memory");
}

__global__ void __launch_bounds__(384, 1) hamming_hy(const float* __restrict__ S,
                                                     int* __restrict__ outi) {
    extern __shared__ __align__(16) char smraw[];
    Smem& sm = *reinterpret_cast<Smem*>(smraw);

    const int tid  = threadIdx.x;
    const int wid  = tid >> 5;
    const int lane = tid & 31;
    const int mtile   = blockIdx.x >> 2;
    const int quarter = blockIdx.x & 3;

    // ---- init: tile-0 cp.async, cntR, Rbits ----
    if (tid < 256) load_B(sm, quarter * NQ, 0, tid);
    sm.cntR[tid % 384] = g_cntR[quarter * 384 + (tid % 384)];   // 384 threads, all slots
    if (tid >= 256) {
        int idx = tid - 256;                 // 0..127
        #pragma unroll
        for (int w = 0; w < 8; w++)
            sm.Rbits[idx * 8 + w] = g_Rbits[(quarter * PR + idx) * 8 + w];
    }
    __syncthreads();

    if (wid < 8) {
        // ================= tensor path =================
        const int g = lane >> 2, q = lane & 3;

        // A fragments (16 rows), contiguous float4 thanks to k-permutation
        uint32_t a[16][4];
        {
            const float* rowLo = S + ((size_t)(mtile * MT + wid * 16 + g)) * KDIM;
            const float* rowHi = rowLo + 8 * KDIM;
            #pragma unroll
            for (int ks = 0; ks < 16; ks++) {
                float4 v0 = *reinterpret_cast<const float4*>(rowLo + ks * 16 + q * 4);
                float4 v1 = *reinterpret_cast<const float4*>(rowHi + ks * 16 + q * 4);
                a[ks][0] = packh2(v0.x, v0.y);
                a[ks][2] = packh2(v0.z, v0.w);
                a[ks][1] = packh2(v1.x, v1.y);
                a[ks][3] = packh2(v1.z, v1.w);
            }
        }

        const float2* cr2 = reinterpret_cast<const float2*>(sm.cntR);
        float rmin0 = __int_as_float(0x7f800000), rmin1 = rmin0;
        int buf = 0;

        for (int t = 0; t < NTILES; t++) {
            asm volatile("bar.sync 1, 256;" ::: "memory");   // all tensor warps done with buf^1
            if (t < NTILES - 1) {
                load_B(sm, quarter * NQ + (t + 1) * NT, buf ^ 1, tid);
                cpwait<1>();
            } else {
                cpwait<0>();
            }

            const char* Bb = sm.B[buf];
            float c[4][4];
            #pragma unroll
            for (int nb = 0; nb < 4; nb++)
                c[nb][0] = c[nb][1] = c[nb][2] = c[nb][3] = 0.f;

            #pragma unroll
            for (int ks = 0; ks < 16; ks++) {
                int kb = ks * 32 + q * 4;
                uint32_t b0[4], b1[4];
                #pragma unroll
                for (int nb = 0; nb < 4; nb++) {
                    const char* bp = &Bb[(nb * 8 + g) * LDB + kb];
                    b0[nb] = *reinterpret_cast<const uint32_t*>(bp);
                    b1[nb] = *reinterpret_cast<const uint32_t*>(bp + 16);
                }
                #pragma unroll
                for (int nb = 0; nb < 4; nb++) mma_f16f32(c[nb], a[ks], b0[nb], b1[nb]);
            }

            #pragma unroll
            for (int nb = 0; nb < 4; nb++) {
                int gcl = t * NT + nb * 8 + q * 2;           // local packed col
                float2 cra = cr2[gcl];
                float2 crb = cr2[gcl + 1];
                decode_min(c[nb][0], cra, rmin0);
                decode_min(c[nb][1], crb, rmin0);
                decode_min(c[nb][2], cra, rmin1);
                decode_min(c[nb][3], crb, rmin1);
            }
            buf ^= 1;
        }

        rmin0 = fminf(rmin0, __shfl_xor_sync(0xffffffffu, rmin0, 1));
        rmin0 = fminf(rmin0, __shfl_xor_sync(0xffffffffu, rmin0, 2));
        rmin1 = fminf(rmin1, __shfl_xor_sync(0xffffffffu, rmin1, 1));
        rmin1 = fminf(rmin1, __shfl_xor_sync(0xffffffffu, rmin1, 2));
        if (q == 0) {
            atomicMin(&outi[mtile * MT + wid * 16 + g],     __float_as_int(rmin0));
            atomicMin(&outi[mtile * MT + wid * 16 + 8 + g], __float_as_int(rmin1));
        }
    } else {
        // ================= popcount path =================
        const int prow = (wid - 8) * 32 + lane;              // 0..127
        const int grow = mtile * MT + prow;
        uint32_t s[8];
        #pragma unroll
        for (int w = 0; w < 8; w++) s[w] = g_Sbits[grow * 8 + w];

        int vmin = 0x7FFFFFFF;
        #pragma unroll 4
        for (int j = 0; j < PR; j++) {
            const uint32_t* r = &sm.Rbits[j * 8];
            int d = 0;
            #pragma unroll
            for (int w = 0; w < 8; w++) d += __popc(s[w] ^ r[w]);
            vmin = min(vmin, d);
        }
        atomicMin(&outi[grow], __float_as_int((float)vmin));
    }
}

// ---------------------------------------------------------------------------
extern "C" void kernel_launch(void* const* d_in, const int* in_sizes, int n_in,
                              void* d_out, int out_size) {
    const float* states = (const float*)d_in[0];
    const float* R      = (const float*)d_in[1];
    int* outi           = (int*)d_out;

    prep_kernel<<<PREP_T / 256, 256>>>(states, R, outi);

    cudaFuncSetAttribute(hamming_hy, cudaFuncAttributeMaxDynamicSharedMemorySize, SMEM_SZ);
    hamming_hy<<<NM * 4, 384, SMEM_SZ>>>(states, outi);
}

// round 12
// speedup vs baseline: 2.1212x; 1.0707x over previous
#include <cuda_runtime.h>
#include <cuda_fp16.h>
#include <cstdint>

#define BATCH 8192
#define NREF  2048
#define KDIM  256
#define MT    128             // M rows per mtile (4 warps x 32 rows)
#define NM    64              // mtiles
#define NPACK 1024            // packed columns (2 refs each)
#define NT    32              // packed cols per work item
#define NITEMS (NM * 32)      // 2048 items = (mtile, chunk)
#define GRID  296             // 2 CTAs x 148 SMs, one balanced wave
#define ROWB  512             // bytes per packed-col row (256 halves)
#define LDB   528             // padded smem row stride (bytes)

// g_Bp[j][k']: k-permuted f16 (1-2R[2j,k]) + 1024*(1-2R[2j+1,k])
__device__ __half g_Bp[NPACK * KDIM];
__device__ float  g_cntR[NREF];

struct Smem {
    char  B[2][NT * LDB];     // 2 x 16896 B
    float cntR[NREF];         // 8192 B
};
#define SMEM_SZ (int)sizeof(Smem)

// ---------------------------------------------------------------------------
__device__ __forceinline__ uint32_t s2u(const void* p) {
    uint32_t a;
    asm("{ .reg .u64 t; cvta.to.shared.u64 t, %1; cvt.u32.u64 %0, t; }" : "=r"(a) : "l"(p));
    return a;
}
__device__ __forceinline__ void cpa16(uint32_t dst, const void* src) {
    asm volatile("cp.async.cg.shared.global [%0], [%1], 16;" :: "r"(dst), "l"(src));
}
template <int N>
__device__ __forceinline__ void cpwait() {
    asm volatile("cp.async.wait_group %0;" :: "n"(N) : "memory");
}
__device__ __forceinline__ void mma_f16f32(float* c, const uint32_t* a,
                                           uint32_t b0, uint32_t b1) {
    asm volatile(
        "mma.sync.aligned.m16n8k16.row.col.f32.f16.f16.f32 "
        "{%0,%1,%2,%3},{%4,%5,%6,%7},{%8,%9},{%0,%1,%2,%3};"
        : "+f"(c[0]), "+f"(c[1]), "+f"(c[2]), "+f"(c[3])
        : "r"(a[0]), "r"(a[1]), "r"(a[2]), "r"(a[3]), "r"(b0), "r"(b1));
}
__device__ __forceinline__ uint32_t packh2(float x, float y) {
    __half2 h = __floats2half2_rn(x, y);
    return *reinterpret_cast<uint32_t*>(&h);
}
__device__ __forceinline__ void decode_min(float acc, float2 cr, float& rmin) {
    float d1 = rintf(acc * (1.0f / 1024.0f));      // |d0|/1024 <= 0.25 -> no ties
    float d0 = fmaf(d1, -1024.0f, acc);            // exact
    rmin = fminf(rmin, fminf(d0 + cr.x, d1 + cr.y));
}

// ---------------------------------------------------------------------------
// Kernel 1 (prep): out init; pack ref pairs (radix 1024, k-permuted so A
// fragments are contiguous float4); cntR. All exact.
// ---------------------------------------------------------------------------
__global__ void prep_kernel(const float* __restrict__ R, int* __restrict__ outi) {
    int i = blockIdx.x * 256 + threadIdx.x;

    if (i < BATCH) outi[i] = 0x7f800000;   // +inf bits

    if (i < NPACK * 64) {                  // one logical k-quad per thread
        int j = i >> 6, c = i & 63;        // packed col j, quad c
        int g16 = c >> 2, q = c & 3;
        float4 r0 = *reinterpret_cast<const float4*>(R + (size_t)(2 * j) * KDIM + c * 4);
        float4 r1 = *reinterpret_cast<const float4*>(R + (size_t)(2 * j + 1) * KDIM + c * 4);
        uint32_t lo = packh2(1025.f - 2.f * r0.x - 2048.f * r1.x,
                             1025.f - 2.f * r0.y - 2048.f * r1.y);
        uint32_t hi = packh2(1025.f - 2.f * r0.z - 2048.f * r1.z,
                             1025.f - 2.f * r0.w - 2048.f * r1.w);
        uint32_t* bp = reinterpret_cast<uint32_t*>(g_Bp);
        bp[j * 128 + g16 * 8 + q]     = lo;
        bp[j * 128 + g16 * 8 + 4 + q] = hi;
    } else if (i < NPACK * 64 + NREF * 32) {
        int t = i - NPACK * 64;
        int w = t >> 5, lane = t & 31;
        float s = 0.f;
        #pragma unroll
        for (int k = lane; k < KDIM; k += 32) s += R[w * KDIM + k];
        #pragma unroll
        for (int o = 16; o; o >>= 1) s += __shfl_xor_sync(0xffffffffu, s, o);
        if (lane == 0) g_cntR[w] = s;
    }
}

// ---------------------------------------------------------------------------
// Kernel 2 (main): statically partitioned persistent HMMA GEMM.
// 2048 items = (mtile, 32-col chunk), mtile-major; CTA b owns the contiguous
// range [b*256/37, (b+1)*256/37) -> 6-7 items, <= 2 distinct mtiles.
// ---------------------------------------------------------------------------
__device__ __forceinline__ void load_B(Smem& sm, int chunk, int buf, int tid) {
    const char* src = (const char*)g_Bp + (size_t)chunk * NT * ROWB;
    #pragma unroll
    for (int j = 0; j < 8; j++) {            // 1024 x 16B chunks / 128 threads
        int i = tid + j * 128;
        int r = i >> 5, c = i & 31;
        cpa16(s2u(&sm.B[buf][r * LDB + c * 16]), src + (size_t)r * ROWB + c * 16);
    }
    asm volatile("cp.async.commit_group;" ::: "memory");
}

__global__ void __launch_bounds__(128, 2) hamming_st(const float* __restrict__ S,
                                                     int* __restrict__ outi) {
    extern __shared__ __align__(16) char smraw[];
    Smem& sm = *reinterpret_cast<Smem*>(smraw);

    const int tid  = threadIdx.x;
    const int wid  = tid >> 5;
    const int lane = tid & 31;
    const int g    = lane >> 2;
    const int q    = lane & 3;

    // static contiguous item range (2048 / 296 = 256 / 37)
    const int start = (blockIdx.x * 256) / 37;
    const int end   = ((blockIdx.x + 1) * 256) / 37;

    int cur_m = start >> 5;

    load_B(sm, start & 31, 0, tid);          // first B tile in flight

    // all 2048 cntR into smem
    for (int i = tid; i < NREF / 4; i += 128)
        *reinterpret_cast<float4*>(&sm.cntR[i * 4]) =
            *reinterpret_cast<const float4*>(&g_cntR[i * 4]);

    // A fragments (2 m16-tiles x 16 ks x 4 regs), contiguous float4 loads
    uint32_t a[2][16][4];
    auto loadA = [&](int m) {
        #pragma unroll
        for (int mt = 0; mt < 2; mt++) {
            const float* rowLo = S + ((size_t)(m * MT + wid * 32 + mt * 16 + g)) * KDIM;
            const float* rowHi = rowLo + 8 * KDIM;
            #pragma unroll
            for (int ks = 0; ks < 16; ks++) {
                float4 v0 = *reinterpret_cast<const float4*>(rowLo + ks * 16 + q * 4);
                float4 v1 = *reinterpret_cast<const float4*>(rowHi + ks * 16 + q * 4);
                a[mt][ks][0] = packh2(v0.x, v0.y);
                a[mt][ks][2] = packh2(v0.z, v0.w);
                a[mt][ks][1] = packh2(v1.x, v1.y);
                a[mt][ks][3] = packh2(v1.z, v1.w);
            }
        }
    };
    loadA(cur_m);

    const float2* cr2 = reinterpret_cast<const float2*>(sm.cntR);
    float rmin[2][2] = {{__int_as_float(0x7f800000), __int_as_float(0x7f800000)},
                        {__int_as_float(0x7f800000), __int_as_float(0x7f800000)}};

    auto flush = [&](int m) {
        #pragma unroll
        for (int mt = 0; mt < 2; mt++)
            #pragma unroll
            for (int h = 0; h < 2; h++) {
                float v = rmin[mt][h];
                v = fminf(v, __shfl_xor_sync(0xffffffffu, v, 1));
                v = fminf(v, __shfl_xor_sync(0xffffffffu, v, 2));
                if (q == 0)
                    atomicMin(&outi[m * MT + wid * 32 + mt * 16 + h * 8 + g],
                              __float_as_int(v));
                rmin[mt][h] = __int_as_float(0x7f800000);
            }
    };

    int buf = 0;
    for (int it = start; it < end; it++) {
        const int cur_c = it & 31;

        if (it + 1 < end) {
            load_B(sm, (it + 1) & 31, buf ^ 1, tid);
            cpwait<1>();
        } else {
            cpwait<0>();
        }
        __syncthreads();

        // ---- MMA on current chunk (32 packed cols = 4 n-blocks) ----
        const char* Bb = sm.B[buf];
        float c[2][4][4];
        #pragma unroll
        for (int mt = 0; mt < 2; mt++)
            #pragma unroll
            for (int u = 0; u < 4; u++)
                c[mt][u][0] = c[mt][u][1] = c[mt][u][2] = c[mt][u][3] = 0.f;

        #pragma unroll
        for (int ks = 0; ks < 16; ks++) {
            int kb = ks * 32 + q * 4;
            uint32_t b0[4], b1[4];
            #pragma unroll
            for (int u = 0; u < 4; u++) {
                const char* bp = &Bb[(u * 8 + g) * LDB + kb];
                b0[u] = *reinterpret_cast<const uint32_t*>(bp);
                b1[u] = *reinterpret_cast<const uint32_t*>(bp + 16);
            }
            #pragma unroll
            for (int u = 0; u < 4; u++) {
                mma_f16f32(c[0][u], a[0][ks], b0[u], b1[u]);
                mma_f16f32(c[1][u], a[1][ks], b0[u], b1[u]);
            }
        }

        // ---- decode epilogue ----
        #pragma unroll
        for (int u = 0; u < 4; u++) {
            int gcol = cur_c * NT + u * 8 + q * 2;
            float2 cra = cr2[gcol];
            float2 crb = cr2[gcol + 1];
            #pragma unroll
            for (int mt = 0; mt < 2; mt++) {
                decode_min(c[mt][u][0], cra, rmin[mt][0]);
                decode_min(c[mt][u][1], crb, rmin[mt][0]);
                decode_min(c[mt][u][2], cra, rmin[mt][1]);
                decode_min(c[mt][u][3], crb, rmin[mt][1]);
            }
        }
        __syncthreads();   // done reading sm.B[buf]; safe to refill next iter

        if (it + 1 < end) {
            int nm = (it + 1) >> 5;
            if (nm != cur_m) { flush(cur_m); loadA(nm); cur_m = nm; }
        }
        buf ^= 1;
    }
    flush(cur_m);
}

// ---------------------------------------------------------------------------
extern "C" void kernel_launch(void* const* d_in, const int* in_sizes, int n_in,
                              void* d_out, int out_size) {
    const float* states = (const float*)d_in[0];
    const float* R      = (const float*)d_in[1];
    int* outi           = (int*)d_out;

    const int prepThreads = NPACK * 64 + NREF * 32;   // 131072
    prep_kernel<<<(prepThreads + 255) / 256, 256>>>(R, outi);

    cudaFuncSetAttribute(hamming_st, cudaFuncAttributeMaxDynamicSharedMemorySize, SMEM_SZ);
    hamming_st<<<GRID, 128, SMEM_SZ>>>(states, outi);
}